// round 1
// baseline (speedup 1.0000x reference)
#include <cuda_runtime.h>
#include <math.h>

// Problem constants
#define T_STEPS 128
#define B_BATCH 256
#define D_IN    512
#define H_DIM   512
#define L_LAYERS 2
#define M_TOTAL (T_STEPS * B_BATCH)          // 32768 rows
#define BH      (B_BATCH * H_DIM)            // 131072
#define TBH     ((size_t)T_STEPS * BH)       // 16777216

// Scratch: static device globals (allocation-free rule)
__device__ float g_F[(size_t)M_TOTAL * H_DIM];   // 64 MB
__device__ float g_C[(size_t)M_TOTAL * H_DIM];   // 64 MB
__device__ float g_H[(size_t)M_TOTAL * H_DIM];   // 64 MB

// ---------------------------------------------------------------------------
// GEMM + activation.
// Computes, for one layer:
//   g_F = sigmoid(A @ Wf^T + bf)   (blockIdx.y 0..3)
//   g_C = relu   (A @ Wi^T + bi)   (blockIdx.y 4..7)
// A: [M_TOTAL, 512] row-major. W: [512, 512] row-major (H x D), i.e. both
// operands K-major -> NT gemm.
// Tile: 128x128 per block, BK=16, 256 threads, 8x8 per thread.
// ---------------------------------------------------------------------------
#define BM 128
#define BN 128
#define BK 16
#define TM 8
#define TN 8

__global__ __launch_bounds__(256, 2)
void gemm_act_kernel(const float* __restrict__ A,
                     const float* __restrict__ Wf,
                     const float* __restrict__ bf,
                     const float* __restrict__ Wi,
                     const float* __restrict__ bi,
                     float* __restrict__ outF,
                     float* __restrict__ outC)
{
    __shared__ float As[BK][BM];
    __shared__ float Bs[BK][BN];

    const int mBlock = blockIdx.x * BM;
    const int yb = blockIdx.y;               // 0..7
    const bool isF = (yb < 4);
    const int n0 = (yb & 3) * BN;
    const float* __restrict__ W    = isF ? Wf : Wi;
    const float* __restrict__ bias = isF ? bf : bi;
    float* __restrict__ dst        = isF ? outF : outC;

    const int tid = threadIdx.x;
    const int tx = tid & 15;                 // 0..15 -> N direction
    const int ty = tid >> 4;                 // 0..15 -> M direction

    float acc[TM][TN];
#pragma unroll
    for (int i = 0; i < TM; i++)
#pragma unroll
        for (int j = 0; j < TN; j++) acc[i][j] = 0.f;

    for (int k0 = 0; k0 < 512; k0 += BK) {
        // Load A tile (128 rows x 16 cols) and W tile, transposed into smem.
        // 512 float4 per tile / 256 threads = 2 each.
#pragma unroll
        for (int r = 0; r < 2; r++) {
            int idx = tid + r * 256;         // 0..511
            int row = idx >> 2;              // 0..127
            int c4  = idx & 3;               // 0..3 (float4 within 16 cols)
            float4 va = *(const float4*)(A + (size_t)(mBlock + row) * 512 + k0 + c4 * 4);
            As[c4 * 4 + 0][row] = va.x;
            As[c4 * 4 + 1][row] = va.y;
            As[c4 * 4 + 2][row] = va.z;
            As[c4 * 4 + 3][row] = va.w;
            float4 vb = *(const float4*)(W + (size_t)(n0 + row) * 512 + k0 + c4 * 4);
            Bs[c4 * 4 + 0][row] = vb.x;
            Bs[c4 * 4 + 1][row] = vb.y;
            Bs[c4 * 4 + 2][row] = vb.z;
            Bs[c4 * 4 + 3][row] = vb.w;
        }
        __syncthreads();

#pragma unroll
        for (int k = 0; k < BK; k++) {
            float ra[TM], rb[TN];
#pragma unroll
            for (int i = 0; i < TM; i++) ra[i] = As[k][ty * TM + i];
#pragma unroll
            for (int j = 0; j < TN; j++) rb[j] = Bs[k][tx * TN + j];
#pragma unroll
            for (int i = 0; i < TM; i++)
#pragma unroll
                for (int j = 0; j < TN; j++)
                    acc[i][j] = fmaf(ra[i], rb[j], acc[i][j]);
        }
        __syncthreads();
    }

    // Epilogue: bias + activation, write [M, 512]
#pragma unroll
    for (int j = 0; j < TN; j++) {
        const int n = n0 + tx * TN + j;
        const float b = bias[n];
#pragma unroll
        for (int i = 0; i < TM; i++) {
            const int m = mBlock + ty * TM + i;
            float z = acc[i][j] + b;
            float o;
            if (isF) o = 1.f / (1.f + expf(-z));   // sigmoid
            else     o = fmaxf(z, 0.f);            // relu
            dst[(size_t)m * H_DIM + n] = o;
        }
    }
}

// ---------------------------------------------------------------------------
// Layer-0 elementwise scan: hidden[t] = F[t]*h + (1-F[t])*C[t]
// One thread per (b, h) element; 128 sequential steps.
// Layer-0 LIF is dead code (its spikes are never consumed) -> skipped.
// ---------------------------------------------------------------------------
__global__ void scan_layer0(const float* __restrict__ F,
                            const float* __restrict__ C,
                            float* __restrict__ Hout,
                            float* __restrict__ hFinal)
{
    const int e = blockIdx.x * blockDim.x + threadIdx.x;   // < BH
    float h = 0.f;
    size_t off = e;
#pragma unroll 4
    for (int t = 0; t < T_STEPS; t++, off += BH) {
        float f = F[off];
        float c = C[off];
        h = f * h + (1.f - f) * c;
        Hout[off] = h;
    }
    hFinal[e] = h;
}

// ---------------------------------------------------------------------------
// Layer-1 scan with LIF dynamics:
//   hidden = F*h + (1-F)*C
//   v      = v + (hidden - v)/2            (tau = 2, decay_input)
//   spike  = (v >= 1)                       (v_th = 1)
//   v     -= spike                          (soft reset)
// Writes spikes[t] and the final hidden state.
// ---------------------------------------------------------------------------
__global__ void scan_layer1(const float* __restrict__ F,
                            const float* __restrict__ C,
                            float* __restrict__ spikes,
                            float* __restrict__ hFinal)
{
    const int e = blockIdx.x * blockDim.x + threadIdx.x;   // < BH
    float h = 0.f;
    float v = 0.f;
    size_t off = e;
#pragma unroll 4
    for (int t = 0; t < T_STEPS; t++, off += BH) {
        float f = F[off];
        float c = C[off];
        h = f * h + (1.f - f) * c;
        v = v + (h - v) * 0.5f;              // exact: /2.0
        float s = (v >= 1.0f) ? 1.0f : 0.0f;
        v -= s;                              // s * V_TH, V_TH = 1
        spikes[off] = s;
    }
    hFinal[e] = h;
}

// ---------------------------------------------------------------------------
// Launch: 2 batched GEMMs + 2 scans.
// Inputs (metadata order): x [T,B,D], Wf [L,H,D], bf [L,H], Wi [L,H,D], bi [L,H]
// Output: spikes [T,B,H] then hT [L,B,H], concatenated fp32.
// ---------------------------------------------------------------------------
extern "C" void kernel_launch(void* const* d_in, const int* in_sizes, int n_in,
                              void* d_out, int out_size)
{
    const float* x  = (const float*)d_in[0];
    const float* Wf = (const float*)d_in[1];
    const float* bf = (const float*)d_in[2];
    const float* Wi = (const float*)d_in[3];
    const float* bi = (const float*)d_in[4];

    float* out    = (float*)d_out;
    float* spikes = out;                      // [T, B, H]
    float* hT     = out + TBH;                // [L, B, H]: layer0 then layer1

    float *pF, *pC, *pH;
    cudaGetSymbolAddress((void**)&pF, g_F);
    cudaGetSymbolAddress((void**)&pC, g_C);
    cudaGetSymbolAddress((void**)&pH, g_H);

    dim3 gemmGrid(M_TOTAL / BM, 8);
    dim3 gemmBlock(256);
    dim3 scanGrid(BH / 256);
    dim3 scanBlock(256);

    // Layer 0: GEMMs on raw x (independent of recurrence), then scan.
    gemm_act_kernel<<<gemmGrid, gemmBlock>>>(
        x, Wf, bf, Wi, bi, pF, pC);
    scan_layer0<<<scanGrid, scanBlock>>>(pF, pC, pH, hT);

    // Layer 1: GEMMs on hidden0 sequence, then scan + LIF.
    const size_t lo = (size_t)H_DIM * D_IN;   // layer stride in W
    gemm_act_kernel<<<gemmGrid, gemmBlock>>>(
        pH, Wf + lo, bf + H_DIM, Wi + lo, bi + H_DIM, pF, pC);
    scan_layer1<<<scanGrid, scanBlock>>>(pF, pC, spikes, hT + BH);
}

// round 5
// speedup vs baseline: 2.6070x; 2.6070x over previous
#include <cuda_runtime.h>
#include <cuda_fp16.h>
#include <math.h>
#include <stdint.h>

// Problem constants
#define T_STEPS 128
#define B_BATCH 256
#define D_IN    512
#define H_DIM   512
#define M_TOTAL (T_STEPS * B_BATCH)          // 32768 rows
#define BH      (B_BATCH * H_DIM)            // 131072
#define TBH     ((size_t)T_STEPS * BH)       // 16777216

// ---------------------------------------------------------------------------
// Scratch (allocation-free rule -> __device__ globals)
// ---------------------------------------------------------------------------
__device__ float g_F[(size_t)M_TOTAL * H_DIM];   // 64 MB
__device__ float g_C[(size_t)M_TOTAL * H_DIM];   // 64 MB
// fp16 split planes, tile-ready pre-swizzled layout:
//   block(tile, stage) = 16KB contiguous = [128 rows x 64 K-cols fp16], SW128
__device__ __align__(16) unsigned char g_Ahi[(size_t)M_TOTAL * 512 * 2];  // 32 MB
__device__ __align__(16) unsigned char g_Alo[(size_t)M_TOTAL * 512 * 2];  // 32 MB
// W planes: per layer, 1024 rows (Wf 0..511, Wi 512..1023) x 512 K
__device__ __align__(16) unsigned char g_Bhi[2u * 1024 * 512 * 2];        // 2 MB
__device__ __align__(16) unsigned char g_Blo[2u * 1024 * 512 * 2];        // 2 MB

// ---------------------------------------------------------------------------
// PTX helpers (plain sm_100-safe: cp.async + ldmatrix + mma.sync only)
// ---------------------------------------------------------------------------
__device__ __forceinline__ uint32_t smem_to_u32(const void* p) {
    uint32_t a;
    asm("{ .reg .u64 t; cvta.to.shared.u64 t, %1; cvt.u32.u64 %0, t; }" : "=r"(a) : "l"(p));
    return a;
}
__device__ __forceinline__ uint32_t sw128(uint32_t off) {
    return off ^ ((off >> 3) & 0x70);
}

#define CP_ASYNC16(sm, gp) \
    asm volatile("cp.async.cg.shared.global [%0], [%1], 16;" :: "r"((uint32_t)(sm)), "l"(gp))
#define CP_ASYNC_COMMIT() asm volatile("cp.async.commit_group;" ::: "memory")
#define CP_ASYNC_WAIT(n)  asm volatile("cp.async.wait_group %0;" :: "n"(n) : "memory")

#define LDMATRIX_X4(r, addr) \
    asm volatile("ldmatrix.sync.aligned.m8n8.x4.shared.b16 {%0,%1,%2,%3}, [%4];" \
        : "=r"((r)[0]), "=r"((r)[1]), "=r"((r)[2]), "=r"((r)[3]) : "r"(addr))
#define LDMATRIX_X2(r, addr) \
    asm volatile("ldmatrix.sync.aligned.m8n8.x2.shared.b16 {%0,%1}, [%2];" \
        : "=r"((r)[0]), "=r"((r)[1]) : "r"(addr))

__device__ __forceinline__ void mma16816(float* c, const uint32_t* a, const uint32_t* b) {
    asm volatile(
        "mma.sync.aligned.m16n8k16.row.col.f32.f16.f16.f32 "
        "{%0,%1,%2,%3}, {%4,%5,%6,%7}, {%8,%9}, {%0,%1,%2,%3};"
        : "+f"(c[0]), "+f"(c[1]), "+f"(c[2]), "+f"(c[3])
        : "r"(a[0]), "r"(a[1]), "r"(a[2]), "r"(a[3]), "r"(b[0]), "r"(b[1]));
}

// ---------------------------------------------------------------------------
// Split helpers: fp32 -> (hi, lo) fp16 planes (lo = residual, UNSCALED),
// tile-ready SW128 layout. block(tile, stage) = 16KB.
// ---------------------------------------------------------------------------
__device__ __forceinline__ void split_store(unsigned char* hiP, unsigned char* loP,
                                            uint32_t block, int r, int kin,
                                            float vx, float vy) {
    __half hx = __float2half_rn(vx);
    __half hy = __float2half_rn(vy);
    __half lx = __float2half_rn(vx - __half2float(hx));
    __half ly = __float2half_rn(vy - __half2float(hy));
    uint32_t off = ((uint32_t)r << 7) + ((uint32_t)kin << 1);
    uint32_t sw = sw128(off);
    uint32_t hw = (uint32_t)__half_as_ushort(hx) | ((uint32_t)__half_as_ushort(hy) << 16);
    uint32_t lw = (uint32_t)__half_as_ushort(lx) | ((uint32_t)__half_as_ushort(ly) << 16);
    *(uint32_t*)(hiP + block + sw) = hw;
    *(uint32_t*)(loP + block + sw) = lw;
}

__global__ void split_A_kernel(const float* __restrict__ src,
                               unsigned char* __restrict__ hiP,
                               unsigned char* __restrict__ loP) {
    const int m = blockIdx.x;                 // 0..32767
    const int k = threadIdx.x << 1;           // 0..510 (pairs)
    float2 v = *(const float2*)(src + (size_t)m * 512 + k);
    const int mtile = m >> 7, r = m & 127, stage = k >> 6, kin = k & 63;
    uint32_t block = (uint32_t)(((mtile << 3) + stage) << 14);
    split_store(hiP, loP, block, r, kin, v.x, v.y);
}

__global__ void split_W_kernel(const float* __restrict__ Wf,
                               const float* __restrict__ Wi,
                               unsigned char* __restrict__ hiP,
                               unsigned char* __restrict__ loP) {
    const int bid = blockIdx.x;               // 0..2047
    const int l = bid >> 10;
    const int n = bid & 1023;                 // 0..511 Wf, 512..1023 Wi
    const int k = threadIdx.x << 1;
    const float* row = (n < 512) ? (Wf + ((size_t)l * 512 + n) * 512)
                                 : (Wi + ((size_t)l * 512 + (n - 512)) * 512);
    float2 v = *(const float2*)(row + k);
    const int ntile = n >> 7, r = n & 127, stage = k >> 6, kin = k & 63;
    uint32_t block = (uint32_t)l * 1048576u + (uint32_t)(((ntile << 3) + stage) << 14);
    split_store(hiP, loP, block, r, kin, v.x, v.y);
}

// ---------------------------------------------------------------------------
// mma.sync GEMM: one 128x128 output tile per CTA of [32768 x 1024].
// ntile (blockIdx.x) 0..3 -> F = sigmoid(A@Wf^T+bf), 4..7 -> C = relu(A@Wi^T+bi)
// 8 warps (2M x 4N), warp tile 64x32. K = 512 in 8 stages of 64.
// THREE-stage cp.async pipeline (192KB smem): 2 stage-copies always in flight
// behind the MMA loop. 3 fp16 products per K-step into ONE fp32 accumulator:
//   acc += Ahi*Bhi + Ahi*Blo + Alo*Bhi      (z error ~5e-6)
// ---------------------------------------------------------------------------
#define GEMM_SMEM (3 * 65536)

__global__ __launch_bounds__(256, 1)
void gemm_tc(const unsigned char* __restrict__ Ahi, const unsigned char* __restrict__ Alo,
             const unsigned char* __restrict__ Bhi, const unsigned char* __restrict__ Blo,
             const float* __restrict__ biasF, const float* __restrict__ biasC,
             float* __restrict__ outF, float* __restrict__ outC) {
    extern __shared__ __align__(1024) unsigned char smem[];
    const uint32_t smem_base = smem_to_u32(smem);
    const int tid = threadIdx.x;
    const int ntile = blockIdx.x;             // 0..7 (x-fast: shares A tile via L2)
    const int mtile = blockIdx.y;             // 0..255

    const int lane = tid & 31;
    const int wid = tid >> 5;
    const int wm = wid & 1;                   // M half (0,1)
    const int wn = wid >> 1;                  // N quarter (0..3)

    const size_t aBase = (size_t)(mtile << 3) << 14;     // 8 stage-blocks of 16KB
    const size_t bBase = (size_t)(ntile << 3) << 14;

    float acc[4][4][4];                       // [mt][nt][frag]
#pragma unroll
    for (int i = 0; i < 4; i++)
#pragma unroll
        for (int j = 0; j < 4; j++)
#pragma unroll
            for (int q = 0; q < 4; q++) acc[i][j][q] = 0.f;

    // Stage copy: 64KB = 4 planes x 16KB; 16 x 16B per thread
    auto load_stage = [&](int s) {
        const uint32_t buf = smem_base + (uint32_t)(s % 3) * 65536u;
        const unsigned char* srcA0 = Ahi + aBase + ((size_t)s << 14);
        const unsigned char* srcA1 = Alo + aBase + ((size_t)s << 14);
        const unsigned char* srcB0 = Bhi + bBase + ((size_t)s << 14);
        const unsigned char* srcB1 = Blo + bBase + ((size_t)s << 14);
#pragma unroll
        for (int i = 0; i < 4; i++) {
            const uint32_t o = (uint32_t)(i * 256 + tid) * 16u;
            CP_ASYNC16(buf + o,         srcA0 + o);
            CP_ASYNC16(buf + 16384 + o, srcA1 + o);
            CP_ASYNC16(buf + 32768 + o, srcB0 + o);
            CP_ASYNC16(buf + 49152 + o, srcB1 + o);
        }
        CP_ASYNC_COMMIT();
    };

    // ldmatrix source offsets (within a 16KB plane): row-major 128 rows x 128B, SW128
    const uint32_t aRow = (uint32_t)(wm * 64 + (lane & 15));       // + mt*16
    const uint32_t aKc  = (uint32_t)((lane >> 4) * 8);             // + k16*16
    const uint32_t bRow = (uint32_t)(wn * 32 + (lane & 7));        // + nt*8
    const uint32_t bKc  = (uint32_t)(((lane >> 3) & 1) * 8);       // + k16*16

    load_stage(0);
    load_stage(1);

    for (int s = 0; s < 8; s++) {
        // Ensure stage s's copy is complete (groups complete in commit order;
        // at this point the newest committed group is s+1).
        if (s < 7) { CP_ASYNC_WAIT(1); } else { CP_ASYNC_WAIT(0); }
        __syncthreads();
        // Prefetch stage s+2 BEFORE compute: buffer (s+2)%3's last consumer was
        // compute(s-1), which all warps finished before the barrier above.
        if (s < 6) load_stage(s + 2);

        const uint32_t buf = smem_base + (uint32_t)(s % 3) * 65536u;
        const uint32_t pAh = buf;
        const uint32_t pAl = buf + 16384;
        const uint32_t pBh = buf + 32768;
        const uint32_t pBl = buf + 49152;

#pragma unroll
        for (int k16 = 0; k16 < 4; k16++) {
            uint32_t ah[4][4], al[4][4], bh[4][2], bl[4][2];
#pragma unroll
            for (int mt = 0; mt < 4; mt++) {
                uint32_t off = ((aRow + mt * 16) << 7) + ((aKc + k16 * 16) << 1);
                uint32_t sw = sw128(off);
                LDMATRIX_X4(ah[mt], pAh + sw);
                LDMATRIX_X4(al[mt], pAl + sw);
            }
#pragma unroll
            for (int nt = 0; nt < 4; nt++) {
                uint32_t off = ((bRow + nt * 8) << 7) + ((bKc + k16 * 16) << 1);
                uint32_t sw = sw128(off);
                LDMATRIX_X2(bh[nt], pBh + sw);
                LDMATRIX_X2(bl[nt], pBl + sw);
            }
#pragma unroll
            for (int mt = 0; mt < 4; mt++)
#pragma unroll
                for (int nt = 0; nt < 4; nt++) {
                    mma16816(acc[mt][nt], ah[mt], bh[nt]);
                    mma16816(acc[mt][nt], ah[mt], bl[nt]);
                    mma16816(acc[mt][nt], al[mt], bh[nt]);
                }
        }
        // No trailing barrier: the head-of-iteration barrier (next s) closes
        // the buffer-reuse hazard (reuse distance is 3 stages).
    }

    // Epilogue: bias + activation, write fp32 [M, 512]
    const bool isF = (ntile < 4);
    const float* __restrict__ bias = isF ? biasF : biasC;
    float* __restrict__ dst = isF ? outF : outC;
    const int ncol0 = (ntile & 3) << 7;

#pragma unroll
    for (int mt = 0; mt < 4; mt++) {
        const int r0 = (mtile << 7) + wm * 64 + mt * 16 + (lane >> 2);
#pragma unroll
        for (int nt = 0; nt < 4; nt++) {
            const int n = ncol0 + wn * 32 + nt * 8 + (lane & 3) * 2;
            const float b0 = bias[n], b1 = bias[n + 1];
            float z0 = acc[mt][nt][0] + b0;
            float z1 = acc[mt][nt][1] + b1;
            float z2 = acc[mt][nt][2] + b0;
            float z3 = acc[mt][nt][3] + b1;
            float2 o01, o23;
            if (isF) {
                o01.x = 1.f / (1.f + expf(-z0));
                o01.y = 1.f / (1.f + expf(-z1));
                o23.x = 1.f / (1.f + expf(-z2));
                o23.y = 1.f / (1.f + expf(-z3));
            } else {
                o01.x = fmaxf(z0, 0.f); o01.y = fmaxf(z1, 0.f);
                o23.x = fmaxf(z2, 0.f); o23.y = fmaxf(z3, 0.f);
            }
            *(float2*)(dst + (size_t)r0 * 512 + n) = o01;
            *(float2*)(dst + (size_t)(r0 + 8) * 512 + n) = o23;
        }
    }
}

// ---------------------------------------------------------------------------
// Layer-0 scan FUSED with the fp16 split for the layer-1 GEMM input:
// emits hi/lo planes directly in tile-ready SW128 layout (no g_H round trip).
// Key invariant: m = t*256 + b, and 256 ≡ 0 (mod 128) -> r = b&127 is
// t-invariant, so the swizzled in-row offset is computed once.
// ---------------------------------------------------------------------------
__global__ void scan_layer0(const float* __restrict__ F, const float* __restrict__ C,
                            unsigned char* __restrict__ hiP,
                            unsigned char* __restrict__ loP,
                            float* __restrict__ hFinal) {
    const int e = blockIdx.x * blockDim.x + threadIdx.x;   // < BH
    const int b = e >> 9;                    // 0..255
    const int n = e & 511;                   // K position for layer-1 A
    const int stage = n >> 6, kin = n & 63;
    const int r = b & 127;
    const uint32_t sw = sw128(((uint32_t)r << 7) + ((uint32_t)kin << 1));
    // block(t) = ((mtile(t)<<3) + stage) << 14, mtile = 2t + (b>>7)
    uint32_t block = (uint32_t)((((b >> 7) << 3) + stage) << 14) + sw;
    const uint32_t blockStep = 16u << 14;    // mtile advances by 2 per t

    float h = 0.f;
    size_t off = e;
#pragma unroll 4
    for (int t = 0; t < T_STEPS; t++, off += BH, block += blockStep) {
        float f = F[off];
        float c = C[off];
        h = f * h + (1.f - f) * c;
        __half hh = __float2half_rn(h);
        __half hl = __float2half_rn(h - __half2float(hh));
        *(unsigned short*)(hiP + block) = __half_as_ushort(hh);
        *(unsigned short*)(loP + block) = __half_as_ushort(hl);
    }
    hFinal[e] = h;
}

// ---------------------------------------------------------------------------
// Layer-1 scan with LIF dynamics.
// ---------------------------------------------------------------------------
__global__ void scan_layer1(const float* __restrict__ F, const float* __restrict__ C,
                            float* __restrict__ spikes, float* __restrict__ hFinal) {
    const int e = blockIdx.x * blockDim.x + threadIdx.x;
    float h = 0.f, v = 0.f;
    size_t off = e;
#pragma unroll 4
    for (int t = 0; t < T_STEPS; t++, off += BH) {
        float f = F[off];
        float c = C[off];
        h = f * h + (1.f - f) * c;
        v = v + (h - v) * 0.5f;
        float sp = (v >= 1.0f) ? 1.0f : 0.0f;
        v -= sp;
        spikes[off] = sp;
    }
    hFinal[e] = h;
}

// ---------------------------------------------------------------------------
// Launch
// ---------------------------------------------------------------------------
extern "C" void kernel_launch(void* const* d_in, const int* in_sizes, int n_in,
                              void* d_out, int out_size) {
    const float* x  = (const float*)d_in[0];
    const float* Wf = (const float*)d_in[1];
    const float* bf = (const float*)d_in[2];
    const float* Wi = (const float*)d_in[3];
    const float* bi = (const float*)d_in[4];

    float* out    = (float*)d_out;
    float* spikes = out;
    float* hT     = out + TBH;

    float *pF, *pC;
    unsigned char *pAh, *pAl, *pBh, *pBl;
    cudaGetSymbolAddress((void**)&pF, g_F);
    cudaGetSymbolAddress((void**)&pC, g_C);
    cudaGetSymbolAddress((void**)&pAh, g_Ahi);
    cudaGetSymbolAddress((void**)&pAl, g_Alo);
    cudaGetSymbolAddress((void**)&pBh, g_Bhi);
    cudaGetSymbolAddress((void**)&pBl, g_Blo);

    cudaFuncSetAttribute(gemm_tc, cudaFuncAttributeMaxDynamicSharedMemorySize, GEMM_SMEM);

    dim3 gemmGrid(8, 256);
    dim3 scanGrid(BH / 256);

    // Weight + input splits
    split_W_kernel<<<2048, 256>>>(Wf, Wi, pBh, pBl);
    split_A_kernel<<<M_TOTAL, 256>>>(x, pAh, pAl);

    // Layer 0: GEMM -> fused scan+split (emits layer-1 A planes directly)
    gemm_tc<<<gemmGrid, 256, GEMM_SMEM>>>(pAh, pAl, pBh, pBl, bf, bi, pF, pC);
    scan_layer0<<<scanGrid, 256>>>(pF, pC, pAh, pAl, hT);

    // Layer 1
    gemm_tc<<<gemmGrid, 256, GEMM_SMEM>>>(pAh, pAl,
                                          pBh + 1048576u, pBl + 1048576u,
                                          bf + H_DIM, bi + H_DIM, pF, pC);
    scan_layer1<<<scanGrid, 256>>>(pF, pC, spikes, hT + BH);
}

// round 7
// speedup vs baseline: 2.6759x; 1.0265x over previous
#include <cuda_runtime.h>
#include <cuda_fp16.h>
#include <math.h>
#include <stdint.h>

// Problem constants
#define T_STEPS 128
#define B_BATCH 256
#define D_IN    512
#define H_DIM   512
#define M_TOTAL (T_STEPS * B_BATCH)          // 32768 rows
#define BH      (B_BATCH * H_DIM)            // 131072
#define TBH     ((size_t)T_STEPS * BH)       // 16777216

// ---------------------------------------------------------------------------
// Scratch (allocation-free rule -> __device__ globals)
// ---------------------------------------------------------------------------
__device__ float g_F[(size_t)M_TOTAL * H_DIM];   // 64 MB
__device__ float g_C[(size_t)M_TOTAL * H_DIM];   // 64 MB
// fp16 split planes, tile-ready pre-swizzled layout:
//   block(tile128, stage) = 16KB contiguous = [128 rows x 64 K-cols fp16], SW128
__device__ __align__(16) unsigned char g_Ahi[(size_t)M_TOTAL * 512 * 2];  // 32 MB
__device__ __align__(16) unsigned char g_Alo[(size_t)M_TOTAL * 512 * 2];  // 32 MB
// W planes: per layer, 1024 rows (Wf 0..511, Wi 512..1023) x 512 K
__device__ __align__(16) unsigned char g_Bhi[2u * 1024 * 512 * 2];        // 2 MB
__device__ __align__(16) unsigned char g_Blo[2u * 1024 * 512 * 2];        // 2 MB

// ---------------------------------------------------------------------------
// PTX helpers (plain sm_100-safe: cp.async + ldmatrix + mma.sync only)
// ---------------------------------------------------------------------------
__device__ __forceinline__ uint32_t smem_to_u32(const void* p) {
    uint32_t a;
    asm("{ .reg .u64 t; cvta.to.shared.u64 t, %1; cvt.u32.u64 %0, t; }" : "=r"(a) : "l"(p));
    return a;
}
__device__ __forceinline__ uint32_t sw128(uint32_t off) {
    return off ^ ((off >> 3) & 0x70);
}

#define CP_ASYNC16(sm, gp) \
    asm volatile("cp.async.cg.shared.global [%0], [%1], 16;" :: "r"((uint32_t)(sm)), "l"(gp))
#define CP_ASYNC_COMMIT() asm volatile("cp.async.commit_group;" ::: "memory")
#define CP_ASYNC_WAIT(n)  asm volatile("cp.async.wait_group %0;" :: "n"(n) : "memory")

#define LDMATRIX_X4(r, addr) \
    asm volatile("ldmatrix.sync.aligned.m8n8.x4.shared.b16 {%0,%1,%2,%3}, [%4];" \
        : "=r"((r)[0]), "=r"((r)[1]), "=r"((r)[2]), "=r"((r)[3]) : "r"(addr))
#define LDMATRIX_X2(r, addr) \
    asm volatile("ldmatrix.sync.aligned.m8n8.x2.shared.b16 {%0,%1}, [%2];" \
        : "=r"((r)[0]), "=r"((r)[1]) : "r"(addr))

__device__ __forceinline__ void mma16816(float* c, const uint32_t* a, const uint32_t* b) {
    asm volatile(
        "mma.sync.aligned.m16n8k16.row.col.f32.f16.f16.f32 "
        "{%0,%1,%2,%3}, {%4,%5,%6,%7}, {%8,%9}, {%0,%1,%2,%3};"
        : "+f"(c[0]), "+f"(c[1]), "+f"(c[2]), "+f"(c[3])
        : "r"(a[0]), "r"(a[1]), "r"(a[2]), "r"(a[3]), "r"(b[0]), "r"(b[1]));
}

// ---------------------------------------------------------------------------
// Split helpers: fp32 -> (hi, lo) fp16 planes (lo = residual, UNSCALED),
// tile-ready SW128 layout. block(tile128, stage) = 16KB.
// ---------------------------------------------------------------------------
__device__ __forceinline__ void split_store(unsigned char* hiP, unsigned char* loP,
                                            uint32_t block, int r, int kin,
                                            float vx, float vy) {
    __half hx = __float2half_rn(vx);
    __half hy = __float2half_rn(vy);
    __half lx = __float2half_rn(vx - __half2float(hx));
    __half ly = __float2half_rn(vy - __half2float(hy));
    uint32_t off = ((uint32_t)r << 7) + ((uint32_t)kin << 1);
    uint32_t sw = sw128(off);
    uint32_t hw = (uint32_t)__half_as_ushort(hx) | ((uint32_t)__half_as_ushort(hy) << 16);
    uint32_t lw = (uint32_t)__half_as_ushort(lx) | ((uint32_t)__half_as_ushort(ly) << 16);
    *(uint32_t*)(hiP + block + sw) = hw;
    *(uint32_t*)(loP + block + sw) = lw;
}

__global__ void split_A_kernel(const float* __restrict__ src,
                               unsigned char* __restrict__ hiP,
                               unsigned char* __restrict__ loP) {
    const int m = blockIdx.x;                 // 0..32767
    const int k = threadIdx.x << 1;           // 0..510 (pairs)
    float2 v = *(const float2*)(src + (size_t)m * 512 + k);
    const int mtile = m >> 7, r = m & 127, stage = k >> 6, kin = k & 63;
    uint32_t block = (uint32_t)(((mtile << 3) + stage) << 14);
    split_store(hiP, loP, block, r, kin, v.x, v.y);
}

__global__ void split_W_kernel(const float* __restrict__ Wf,
                               const float* __restrict__ Wi,
                               unsigned char* __restrict__ hiP,
                               unsigned char* __restrict__ loP) {
    const int bid = blockIdx.x;               // 0..2047
    const int l = bid >> 10;
    const int n = bid & 1023;                 // 0..511 Wf, 512..1023 Wi
    const int k = threadIdx.x << 1;
    const float* row = (n < 512) ? (Wf + ((size_t)l * 512 + n) * 512)
                                 : (Wi + ((size_t)l * 512 + (n - 512)) * 512);
    float2 v = *(const float2*)(row + k);
    const int ntile = n >> 7, r = n & 127, stage = k >> 6, kin = k & 63;
    uint32_t block = (uint32_t)l * 1048576u + (uint32_t)(((ntile << 3) + stage) << 14);
    split_store(hiP, loP, block, r, kin, v.x, v.y);
}

// ---------------------------------------------------------------------------
// mma.sync GEMM: one 128x256 output tile per CTA of [32768 x 1024].
// ntile (blockIdx.x): 0..1 -> F = sigmoid(A@Wf^T+bf), 2..3 -> C = relu(...)
// 8 warps (2M x 4N), warp tile 64x64. K = 512 in 8 stages of 64.
// 2-stage cp.async double buffer (R3-proven loop structure), 96KB/stage.
// 3 fp16 products per K-step into ONE fp32 accumulator:
//   acc += Ahi*Bhi + Ahi*Blo + Alo*Bhi      (z error ~5e-6)
// L1 economy: 64 ldmatrix wavefronts per k16 for 96 MMAs (0.67 wf/MMA,
// was 1.0 at the 128x128 tile) -- targets the measured L1=65% bottleneck.
// ---------------------------------------------------------------------------
#define STAGE_BYTES 98304u                    // 6 x 16KB planes
#define GEMM_SMEM (2 * 98304)

__global__ __launch_bounds__(256, 1)
void gemm_tc(const unsigned char* __restrict__ Ahi, const unsigned char* __restrict__ Alo,
             const unsigned char* __restrict__ Bhi, const unsigned char* __restrict__ Blo,
             const float* __restrict__ biasF, const float* __restrict__ biasC,
             float* __restrict__ outF, float* __restrict__ outC) {
    extern __shared__ __align__(1024) unsigned char smem[];
    const uint32_t smem_base = smem_to_u32(smem);
    const int tid = threadIdx.x;
    const int ntile = blockIdx.x;             // 0..3 (x-fast: shares A tile via L2)
    const int mtile = blockIdx.y;             // 0..255

    const int lane = tid & 31;
    const int wid = tid >> 5;
    const int wm = wid & 1;                   // M half (0,1) -> 64 rows
    const int wn = wid >> 1;                  // N quarter (0..3) -> 64 cols

    const size_t aBase = (size_t)mtile * 131072u;          // 8 stage-blocks of 16KB
    const size_t bBase = (size_t)ntile * 262144u;          // two 128-row blocks

    float acc[4][8][4];                       // [mt][nt][frag] = 128 regs
#pragma unroll
    for (int i = 0; i < 4; i++)
#pragma unroll
        for (int j = 0; j < 8; j++)
#pragma unroll
            for (int q = 0; q < 4; q++) acc[i][j][q] = 0.f;

    // Stage copy: 96KB = 6 planes x 16KB; 24 x 16B per thread
    auto load_stage = [&](int s) {
        const uint32_t buf = smem_base + (uint32_t)(s & 1) * STAGE_BYTES;
        const size_t so = (size_t)s << 14;
        const unsigned char* p0 = Ahi + aBase + so;             // A hi
        const unsigned char* p1 = Alo + aBase + so;             // A lo
        const unsigned char* p2 = Bhi + bBase + so;             // B hi rows 0..127
        const unsigned char* p3 = Bhi + bBase + 131072u + so;   // B hi rows 128..255
        const unsigned char* p4 = Blo + bBase + so;             // B lo rows 0..127
        const unsigned char* p5 = Blo + bBase + 131072u + so;   // B lo rows 128..255
#pragma unroll
        for (int i = 0; i < 4; i++) {
            const uint32_t o = (uint32_t)(i * 256 + tid) * 16u;
            CP_ASYNC16(buf + o,          p0 + o);
            CP_ASYNC16(buf + 16384 + o,  p1 + o);
            CP_ASYNC16(buf + 32768 + o,  p2 + o);
            CP_ASYNC16(buf + 49152 + o,  p3 + o);
            CP_ASYNC16(buf + 65536 + o,  p4 + o);
            CP_ASYNC16(buf + 81920 + o,  p5 + o);
        }
        CP_ASYNC_COMMIT();
    };

    // ldmatrix source coords
    const uint32_t aRow = (uint32_t)(wm * 64 + (lane & 15));       // + mt*16
    const uint32_t aKc  = (uint32_t)((lane >> 4) * 8);             // + k16*16
    const uint32_t bRowBase = (uint32_t)(wn * 64 + (lane & 7));    // + nt*8 (0..255)
    const uint32_t bKc  = (uint32_t)(((lane >> 3) & 1) * 8);       // + k16*16

    load_stage(0);

    for (int s = 0; s < 8; s++) {
        if (s < 7) load_stage(s + 1);
        if (s < 7) { CP_ASYNC_WAIT(1); } else { CP_ASYNC_WAIT(0); }
        __syncthreads();

        const uint32_t buf = smem_base + (uint32_t)(s & 1) * STAGE_BYTES;
        const uint32_t pAh = buf;
        const uint32_t pAl = buf + 16384;
        const uint32_t pBh = buf + 32768;     // 32KB: two 16KB row-halves
        const uint32_t pBl = buf + 65536;

#pragma unroll
        for (int k16 = 0; k16 < 4; k16++) {
            uint32_t ah[4][4], al[4][4];
#pragma unroll
            for (int mt = 0; mt < 4; mt++) {
                uint32_t off = ((aRow + mt * 16) << 7) + ((aKc + k16 * 16) << 1);
                uint32_t sw = sw128(off);
                LDMATRIX_X4(ah[mt], pAh + sw);
                LDMATRIX_X4(al[mt], pAl + sw);
            }
            // nt in two halves of 4 to bound live B fragments
#pragma unroll
            for (int half = 0; half < 2; half++) {
                uint32_t bh[4][2], bl[4][2];
#pragma unroll
                for (int j = 0; j < 4; j++) {
                    uint32_t row = bRowBase + (half * 4 + j) * 8;   // 0..255
                    uint32_t off = ((row >> 7) << 14)
                                 + sw128(((row & 127) << 7) + ((bKc + k16 * 16) << 1));
                    LDMATRIX_X2(bh[j], pBh + off);
                    LDMATRIX_X2(bl[j], pBl + off);
                }
#pragma unroll
                for (int mt = 0; mt < 4; mt++)
#pragma unroll
                    for (int j = 0; j < 4; j++) {
                        float* a = acc[mt][half * 4 + j];
                        mma16816(a, ah[mt], bh[j]);
                        mma16816(a, ah[mt], bl[j]);
                        mma16816(a, al[mt], bh[j]);
                    }
            }
        }
        __syncthreads();
    }

    // Epilogue: bias + activation, write fp32 [M, 512]
    const bool isF = (ntile < 2);
    const float* __restrict__ bias = isF ? biasF : biasC;
    float* __restrict__ dst = isF ? outF : outC;
    const int ncol0 = (ntile & 1) << 8;       // 0 or 256

#pragma unroll
    for (int mt = 0; mt < 4; mt++) {
        const int r0 = (mtile << 7) + wm * 64 + mt * 16 + (lane >> 2);
#pragma unroll
        for (int nt = 0; nt < 8; nt++) {
            const int n = ncol0 + wn * 64 + nt * 8 + (lane & 3) * 2;
            const float b0 = bias[n], b1 = bias[n + 1];
            float z0 = acc[mt][nt][0] + b0;
            float z1 = acc[mt][nt][1] + b1;
            float z2 = acc[mt][nt][2] + b0;
            float z3 = acc[mt][nt][3] + b1;
            float2 o01, o23;
            if (isF) {
                o01.x = 1.f / (1.f + expf(-z0));
                o01.y = 1.f / (1.f + expf(-z1));
                o23.x = 1.f / (1.f + expf(-z2));
                o23.y = 1.f / (1.f + expf(-z3));
            } else {
                o01.x = fmaxf(z0, 0.f); o01.y = fmaxf(z1, 0.f);
                o23.x = fmaxf(z2, 0.f); o23.y = fmaxf(z3, 0.f);
            }
            *(float2*)(dst + (size_t)r0 * 512 + n) = o01;
            *(float2*)(dst + (size_t)(r0 + 8) * 512 + n) = o23;
        }
    }
}

// ---------------------------------------------------------------------------
// Layer-0 scan FUSED with the fp16 split for the layer-1 GEMM input:
// emits hi/lo planes directly in tile-ready SW128 layout (no g_H round trip).
// r = b&127 is t-invariant, so the swizzled in-row offset is computed once.
// ---------------------------------------------------------------------------
__global__ void scan_layer0(const float* __restrict__ F, const float* __restrict__ C,
                            unsigned char* __restrict__ hiP,
                            unsigned char* __restrict__ loP,
                            float* __restrict__ hFinal) {
    const int e = blockIdx.x * blockDim.x + threadIdx.x;   // < BH
    const int b = e >> 9;                    // 0..255
    const int n = e & 511;                   // K position for layer-1 A
    const int stage = n >> 6, kin = n & 63;
    const int r = b & 127;
    const uint32_t sw = sw128(((uint32_t)r << 7) + ((uint32_t)kin << 1));
    uint32_t block = (uint32_t)((((b >> 7) << 3) + stage) << 14) + sw;
    const uint32_t blockStep = 16u << 14;    // mtile advances by 2 per t

    float h = 0.f;
    size_t off = e;
#pragma unroll 4
    for (int t = 0; t < T_STEPS; t++, off += BH, block += blockStep) {
        float f = F[off];
        float c = C[off];
        h = f * h + (1.f - f) * c;
        __half hh = __float2half_rn(h);
        __half hl = __float2half_rn(h - __half2float(hh));
        *(unsigned short*)(hiP + block) = __half_as_ushort(hh);
        *(unsigned short*)(loP + block) = __half_as_ushort(hl);
    }
    hFinal[e] = h;
}

// ---------------------------------------------------------------------------
// Layer-1 scan with LIF dynamics.
// ---------------------------------------------------------------------------
__global__ void scan_layer1(const float* __restrict__ F, const float* __restrict__ C,
                            float* __restrict__ spikes, float* __restrict__ hFinal) {
    const int e = blockIdx.x * blockDim.x + threadIdx.x;
    float h = 0.f, v = 0.f;
    size_t off = e;
#pragma unroll 4
    for (int t = 0; t < T_STEPS; t++, off += BH) {
        float f = F[off];
        float c = C[off];
        h = f * h + (1.f - f) * c;
        v = v + (h - v) * 0.5f;
        float sp = (v >= 1.0f) ? 1.0f : 0.0f;
        v -= sp;
        spikes[off] = sp;
    }
    hFinal[e] = h;
}

// ---------------------------------------------------------------------------
// Launch
// ---------------------------------------------------------------------------
extern "C" void kernel_launch(void* const* d_in, const int* in_sizes, int n_in,
                              void* d_out, int out_size) {
    const float* x  = (const float*)d_in[0];
    const float* Wf = (const float*)d_in[1];
    const float* bf = (const float*)d_in[2];
    const float* Wi = (const float*)d_in[3];
    const float* bi = (const float*)d_in[4];

    float* out    = (float*)d_out;
    float* spikes = out;
    float* hT     = out + TBH;

    float *pF, *pC;
    unsigned char *pAh, *pAl, *pBh, *pBl;
    cudaGetSymbolAddress((void**)&pF, g_F);
    cudaGetSymbolAddress((void**)&pC, g_C);
    cudaGetSymbolAddress((void**)&pAh, g_Ahi);
    cudaGetSymbolAddress((void**)&pAl, g_Alo);
    cudaGetSymbolAddress((void**)&pBh, g_Bhi);
    cudaGetSymbolAddress((void**)&pBl, g_Blo);

    cudaFuncSetAttribute(gemm_tc, cudaFuncAttributeMaxDynamicSharedMemorySize, GEMM_SMEM);

    dim3 gemmGrid(4, 256);
    dim3 scanGrid(BH / 256);

    // Weight + input splits
    split_W_kernel<<<2048, 256>>>(Wf, Wi, pBh, pBl);
    split_A_kernel<<<M_TOTAL, 256>>>(x, pAh, pAl);

    // Layer 0: GEMM -> fused scan+split (emits layer-1 A planes directly)
    gemm_tc<<<gemmGrid, 256, GEMM_SMEM>>>(pAh, pAl, pBh, pBl, bf, bi, pF, pC);
    scan_layer0<<<scanGrid, 256>>>(pF, pC, pAh, pAl, hT);

    // Layer 1
    gemm_tc<<<gemmGrid, 256, GEMM_SMEM>>>(pAh, pAl,
                                          pBh + 1048576u, pBl + 1048576u,
                                          bf + H_DIM, bi + H_DIM, pF, pC);
    scan_layer1<<<scanGrid, 256>>>(pF, pC, spikes, hT + BH);
}

// round 8
// speedup vs baseline: 2.7237x; 1.0179x over previous
#include <cuda_runtime.h>
#include <cuda_fp16.h>
#include <math.h>
#include <stdint.h>

// Problem constants
#define T_STEPS 128
#define B_BATCH 256
#define D_IN    512
#define H_DIM   512
#define M_TOTAL (T_STEPS * B_BATCH)          // 32768 rows
#define BH      (B_BATCH * H_DIM)            // 131072
#define TBH     ((size_t)T_STEPS * BH)       // 16777216

// ---------------------------------------------------------------------------
// Scratch (allocation-free rule -> __device__ globals)
// ---------------------------------------------------------------------------
__device__ float g_F[(size_t)M_TOTAL * H_DIM];   // 64 MB
__device__ float g_C[(size_t)M_TOTAL * H_DIM];   // 64 MB
// fp16 split planes, tile-ready pre-swizzled layout:
//   block(tile128, stage) = 16KB contiguous = [128 rows x 64 K-cols fp16], SW128
__device__ __align__(16) unsigned char g_Ahi[(size_t)M_TOTAL * 512 * 2];  // 32 MB
__device__ __align__(16) unsigned char g_Alo[(size_t)M_TOTAL * 512 * 2];  // 32 MB
// W planes: per layer, 1024 rows (Wf 0..511, Wi 512..1023) x 512 K
__device__ __align__(16) unsigned char g_Bhi[2u * 1024 * 512 * 2];        // 2 MB
__device__ __align__(16) unsigned char g_Blo[2u * 1024 * 512 * 2];        // 2 MB

// ---------------------------------------------------------------------------
// PTX helpers (plain sm_100-safe: cp.async + ldmatrix + mma.sync only)
// ---------------------------------------------------------------------------
__device__ __forceinline__ uint32_t smem_to_u32(const void* p) {
    uint32_t a;
    asm("{ .reg .u64 t; cvta.to.shared.u64 t, %1; cvt.u32.u64 %0, t; }" : "=r"(a) : "l"(p));
    return a;
}
__device__ __forceinline__ uint32_t sw128(uint32_t off) {
    return off ^ ((off >> 3) & 0x70);
}

#define CP_ASYNC16(sm, gp) \
    asm volatile("cp.async.cg.shared.global [%0], [%1], 16;" :: "r"((uint32_t)(sm)), "l"(gp))
#define CP_ASYNC_COMMIT() asm volatile("cp.async.commit_group;" ::: "memory")
#define CP_ASYNC_WAIT(n)  asm volatile("cp.async.wait_group %0;" :: "n"(n) : "memory")

#define LDMATRIX_X4(r, addr) \
    asm volatile("ldmatrix.sync.aligned.m8n8.x4.shared.b16 {%0,%1,%2,%3}, [%4];" \
        : "=r"((r)[0]), "=r"((r)[1]), "=r"((r)[2]), "=r"((r)[3]) : "r"(addr))
#define LDMATRIX_X2(r, addr) \
    asm volatile("ldmatrix.sync.aligned.m8n8.x2.shared.b16 {%0,%1}, [%2];" \
        : "=r"((r)[0]), "=r"((r)[1]) : "r"(addr))

__device__ __forceinline__ void mma16816(float* c, const uint32_t* a, const uint32_t* b) {
    asm volatile(
        "mma.sync.aligned.m16n8k16.row.col.f32.f16.f16.f32 "
        "{%0,%1,%2,%3}, {%4,%5,%6,%7}, {%8,%9}, {%0,%1,%2,%3};"
        : "+f"(c[0]), "+f"(c[1]), "+f"(c[2]), "+f"(c[3])
        : "r"(a[0]), "r"(a[1]), "r"(a[2]), "r"(a[3]), "r"(b[0]), "r"(b[1]));
}

// ---------------------------------------------------------------------------
// Split helpers: fp32 -> (hi, lo) fp16 planes (lo = residual, UNSCALED),
// tile-ready SW128 layout. block(tile128, stage) = 16KB.
// ---------------------------------------------------------------------------
__device__ __forceinline__ void split_store(unsigned char* hiP, unsigned char* loP,
                                            uint32_t block, int r, int kin,
                                            float vx, float vy) {
    __half hx = __float2half_rn(vx);
    __half hy = __float2half_rn(vy);
    __half lx = __float2half_rn(vx - __half2float(hx));
    __half ly = __float2half_rn(vy - __half2float(hy));
    uint32_t off = ((uint32_t)r << 7) + ((uint32_t)kin << 1);
    uint32_t sw = sw128(off);
    uint32_t hw = (uint32_t)__half_as_ushort(hx) | ((uint32_t)__half_as_ushort(hy) << 16);
    uint32_t lw = (uint32_t)__half_as_ushort(lx) | ((uint32_t)__half_as_ushort(ly) << 16);
    *(uint32_t*)(hiP + block + sw) = hw;
    *(uint32_t*)(loP + block + sw) = lw;
}

__global__ void split_A_kernel(const float* __restrict__ src,
                               unsigned char* __restrict__ hiP,
                               unsigned char* __restrict__ loP) {
    const int m = blockIdx.x;                 // 0..32767
    const int k = threadIdx.x << 1;           // 0..510 (pairs)
    float2 v = *(const float2*)(src + (size_t)m * 512 + k);
    const int mtile = m >> 7, r = m & 127, stage = k >> 6, kin = k & 63;
    uint32_t block = (uint32_t)(((mtile << 3) + stage) << 14);
    split_store(hiP, loP, block, r, kin, v.x, v.y);
}

__global__ void split_W_kernel(const float* __restrict__ Wf,
                               const float* __restrict__ Wi,
                               unsigned char* __restrict__ hiP,
                               unsigned char* __restrict__ loP) {
    const int bid = blockIdx.x;               // 0..2047
    const int l = bid >> 10;
    const int n = bid & 1023;                 // 0..511 Wf, 512..1023 Wi
    const int k = threadIdx.x << 1;
    const float* row = (n < 512) ? (Wf + ((size_t)l * 512 + n) * 512)
                                 : (Wi + ((size_t)l * 512 + (n - 512)) * 512);
    float2 v = *(const float2*)(row + k);
    const int ntile = n >> 7, r = n & 127, stage = k >> 6, kin = k & 63;
    uint32_t block = (uint32_t)l * 1048576u + (uint32_t)(((ntile << 3) + stage) << 14);
    split_store(hiP, loP, block, r, kin, v.x, v.y);
}

// ---------------------------------------------------------------------------
// mma.sync GEMM: one 128x256 output tile per CTA of [32768 x 1024].
// ntile (blockIdx.x): 0..1 -> F = sigmoid(A@Wf^T+bf), 2..3 -> C = relu(...)
// *** R8: 512 threads / 16 warps (4M x 4N, warp tile 32x64) ***
// Rationale: 1 CTA/SM (192KB smem) previously ran 8 warps = 2/SMSP -> tensor
// pipe capped at 58% by latency/sync bubbles. 16 warps = 4/SMSP doubles
// latency hiding at identical tile economics and data layout.
// K = 512 in 8 stages of 64; 2-stage cp.async double buffer (96KB/stage).
// 3 fp16 products per K-step into ONE fp32 accumulator:
//   acc += Ahi*Bhi + Ahi*Blo + Alo*Bhi      (z error ~5e-6)
// ---------------------------------------------------------------------------
#define STAGE_BYTES 98304u                    // 6 x 16KB planes
#define GEMM_SMEM (2 * 98304)

__global__ __launch_bounds__(512, 1)
void gemm_tc(const unsigned char* __restrict__ Ahi, const unsigned char* __restrict__ Alo,
             const unsigned char* __restrict__ Bhi, const unsigned char* __restrict__ Blo,
             const float* __restrict__ biasF, const float* __restrict__ biasC,
             float* __restrict__ outF, float* __restrict__ outC) {
    extern __shared__ __align__(1024) unsigned char smem[];
    const uint32_t smem_base = smem_to_u32(smem);
    const int tid = threadIdx.x;
    const int ntile = blockIdx.x;             // 0..3 (x-fast: shares A tile via L2)
    const int mtile = blockIdx.y;             // 0..255

    const int lane = tid & 31;
    const int wid = tid >> 5;                 // 0..15
    const int wm = wid & 3;                   // M quarter (0..3) -> 32 rows
    const int wn = wid >> 2;                  // N quarter (0..3) -> 64 cols

    const size_t aBase = (size_t)mtile * 131072u;          // 8 stage-blocks of 16KB
    const size_t bBase = (size_t)ntile * 262144u;          // two 128-row blocks

    float acc[2][8][4];                       // [mt][nt][frag] = 64 regs
#pragma unroll
    for (int i = 0; i < 2; i++)
#pragma unroll
        for (int j = 0; j < 8; j++)
#pragma unroll
            for (int q = 0; q < 4; q++) acc[i][j][q] = 0.f;

    // Stage copy: 96KB = 6 planes x 16KB; 12 x 16B per thread (512 threads)
    auto load_stage = [&](int s) {
        const uint32_t buf = smem_base + (uint32_t)(s & 1) * STAGE_BYTES;
        const size_t so = (size_t)s << 14;
        const unsigned char* p0 = Ahi + aBase + so;             // A hi
        const unsigned char* p1 = Alo + aBase + so;             // A lo
        const unsigned char* p2 = Bhi + bBase + so;             // B hi rows 0..127
        const unsigned char* p3 = Bhi + bBase + 131072u + so;   // B hi rows 128..255
        const unsigned char* p4 = Blo + bBase + so;             // B lo rows 0..127
        const unsigned char* p5 = Blo + bBase + 131072u + so;   // B lo rows 128..255
#pragma unroll
        for (int i = 0; i < 2; i++) {
            const uint32_t o = (uint32_t)(i * 512 + tid) * 16u;
            CP_ASYNC16(buf + o,          p0 + o);
            CP_ASYNC16(buf + 16384 + o,  p1 + o);
            CP_ASYNC16(buf + 32768 + o,  p2 + o);
            CP_ASYNC16(buf + 49152 + o,  p3 + o);
            CP_ASYNC16(buf + 65536 + o,  p4 + o);
            CP_ASYNC16(buf + 81920 + o,  p5 + o);
        }
        CP_ASYNC_COMMIT();
    };

    // ldmatrix source coords
    const uint32_t aRow = (uint32_t)(wm * 32 + (lane & 15));       // + mt*16
    const uint32_t aKc  = (uint32_t)((lane >> 4) * 8);             // + k16*16
    const uint32_t bRowBase = (uint32_t)(wn * 64 + (lane & 7));    // + nt*8 (0..255)
    const uint32_t bKc  = (uint32_t)(((lane >> 3) & 1) * 8);       // + k16*16

    load_stage(0);

    for (int s = 0; s < 8; s++) {
        if (s < 7) load_stage(s + 1);
        if (s < 7) { CP_ASYNC_WAIT(1); } else { CP_ASYNC_WAIT(0); }
        __syncthreads();

        const uint32_t buf = smem_base + (uint32_t)(s & 1) * STAGE_BYTES;
        const uint32_t pAh = buf;
        const uint32_t pAl = buf + 16384;
        const uint32_t pBh = buf + 32768;     // 32KB: two 16KB row-halves
        const uint32_t pBl = buf + 65536;

#pragma unroll
        for (int k16 = 0; k16 < 4; k16++) {
            uint32_t ah[2][4], al[2][4];
#pragma unroll
            for (int mt = 0; mt < 2; mt++) {
                uint32_t off = ((aRow + mt * 16) << 7) + ((aKc + k16 * 16) << 1);
                uint32_t sw = sw128(off);
                LDMATRIX_X4(ah[mt], pAh + sw);
                LDMATRIX_X4(al[mt], pAl + sw);
            }
            // nt in two halves of 4 to bound live B fragments (reg budget 128)
#pragma unroll
            for (int half = 0; half < 2; half++) {
                uint32_t bh[4][2], bl[4][2];
#pragma unroll
                for (int j = 0; j < 4; j++) {
                    uint32_t row = bRowBase + (half * 4 + j) * 8;   // 0..255
                    uint32_t off = ((row >> 7) << 14)
                                 + sw128(((row & 127) << 7) + ((bKc + k16 * 16) << 1));
                    LDMATRIX_X2(bh[j], pBh + off);
                    LDMATRIX_X2(bl[j], pBl + off);
                }
#pragma unroll
                for (int mt = 0; mt < 2; mt++)
#pragma unroll
                    for (int j = 0; j < 4; j++) {
                        float* a = acc[mt][half * 4 + j];
                        mma16816(a, ah[mt], bh[j]);
                        mma16816(a, ah[mt], bl[j]);
                        mma16816(a, al[mt], bh[j]);
                    }
            }
        }
        __syncthreads();
    }

    // Epilogue: bias + activation, write fp32 [M, 512]
    const bool isF = (ntile < 2);
    const float* __restrict__ bias = isF ? biasF : biasC;
    float* __restrict__ dst = isF ? outF : outC;
    const int ncol0 = (ntile & 1) << 8;       // 0 or 256

#pragma unroll
    for (int mt = 0; mt < 2; mt++) {
        const int r0 = (mtile << 7) + wm * 32 + mt * 16 + (lane >> 2);
#pragma unroll
        for (int nt = 0; nt < 8; nt++) {
            const int n = ncol0 + wn * 64 + nt * 8 + (lane & 3) * 2;
            const float b0 = bias[n], b1 = bias[n + 1];
            float z0 = acc[mt][nt][0] + b0;
            float z1 = acc[mt][nt][1] + b1;
            float z2 = acc[mt][nt][2] + b0;
            float z3 = acc[mt][nt][3] + b1;
            float2 o01, o23;
            if (isF) {
                o01.x = 1.f / (1.f + expf(-z0));
                o01.y = 1.f / (1.f + expf(-z1));
                o23.x = 1.f / (1.f + expf(-z2));
                o23.y = 1.f / (1.f + expf(-z3));
            } else {
                o01.x = fmaxf(z0, 0.f); o01.y = fmaxf(z1, 0.f);
                o23.x = fmaxf(z2, 0.f); o23.y = fmaxf(z3, 0.f);
            }
            *(float2*)(dst + (size_t)r0 * 512 + n) = o01;
            *(float2*)(dst + (size_t)(r0 + 8) * 512 + n) = o23;
        }
    }
}

// ---------------------------------------------------------------------------
// Layer-0 scan FUSED with the fp16 split for the layer-1 GEMM input:
// emits hi/lo planes directly in tile-ready SW128 layout (no g_H round trip).
// r = b&127 is t-invariant, so the swizzled in-row offset is computed once.
// ---------------------------------------------------------------------------
__global__ void scan_layer0(const float* __restrict__ F, const float* __restrict__ C,
                            unsigned char* __restrict__ hiP,
                            unsigned char* __restrict__ loP,
                            float* __restrict__ hFinal) {
    const int e = blockIdx.x * blockDim.x + threadIdx.x;   // < BH
    const int b = e >> 9;                    // 0..255
    const int n = e & 511;                   // K position for layer-1 A
    const int stage = n >> 6, kin = n & 63;
    const int r = b & 127;
    const uint32_t sw = sw128(((uint32_t)r << 7) + ((uint32_t)kin << 1));
    uint32_t block = (uint32_t)((((b >> 7) << 3) + stage) << 14) + sw;
    const uint32_t blockStep = 16u << 14;    // mtile advances by 2 per t

    float h = 0.f;
    size_t off = e;
#pragma unroll 4
    for (int t = 0; t < T_STEPS; t++, off += BH, block += blockStep) {
        float f = F[off];
        float c = C[off];
        h = f * h + (1.f - f) * c;
        __half hh = __float2half_rn(h);
        __half hl = __float2half_rn(h - __half2float(hh));
        *(unsigned short*)(hiP + block) = __half_as_ushort(hh);
        *(unsigned short*)(loP + block) = __half_as_ushort(hl);
    }
    hFinal[e] = h;
}

// ---------------------------------------------------------------------------
// Layer-1 scan with LIF dynamics.
// ---------------------------------------------------------------------------
__global__ void scan_layer1(const float* __restrict__ F, const float* __restrict__ C,
                            float* __restrict__ spikes, float* __restrict__ hFinal) {
    const int e = blockIdx.x * blockDim.x + threadIdx.x;
    float h = 0.f, v = 0.f;
    size_t off = e;
#pragma unroll 4
    for (int t = 0; t < T_STEPS; t++, off += BH) {
        float f = F[off];
        float c = C[off];
        h = f * h + (1.f - f) * c;
        v = v + (h - v) * 0.5f;
        float sp = (v >= 1.0f) ? 1.0f : 0.0f;
        v -= sp;
        spikes[off] = sp;
    }
    hFinal[e] = h;
}

// ---------------------------------------------------------------------------
// Launch
// ---------------------------------------------------------------------------
extern "C" void kernel_launch(void* const* d_in, const int* in_sizes, int n_in,
                              void* d_out, int out_size) {
    const float* x  = (const float*)d_in[0];
    const float* Wf = (const float*)d_in[1];
    const float* bf = (const float*)d_in[2];
    const float* Wi = (const float*)d_in[3];
    const float* bi = (const float*)d_in[4];

    float* out    = (float*)d_out;
    float* spikes = out;
    float* hT     = out + TBH;

    float *pF, *pC;
    unsigned char *pAh, *pAl, *pBh, *pBl;
    cudaGetSymbolAddress((void**)&pF, g_F);
    cudaGetSymbolAddress((void**)&pC, g_C);
    cudaGetSymbolAddress((void**)&pAh, g_Ahi);
    cudaGetSymbolAddress((void**)&pAl, g_Alo);
    cudaGetSymbolAddress((void**)&pBh, g_Bhi);
    cudaGetSymbolAddress((void**)&pBl, g_Blo);

    cudaFuncSetAttribute(gemm_tc, cudaFuncAttributeMaxDynamicSharedMemorySize, GEMM_SMEM);

    dim3 gemmGrid(4, 256);
    dim3 scanGrid(BH / 256);

    // Weight + input splits
    split_W_kernel<<<2048, 256>>>(Wf, Wi, pBh, pBl);
    split_A_kernel<<<M_TOTAL, 256>>>(x, pAh, pAl);

    // Layer 0: GEMM -> fused scan+split (emits layer-1 A planes directly)
    gemm_tc<<<gemmGrid, 512, GEMM_SMEM>>>(pAh, pAl, pBh, pBl, bf, bi, pF, pC);
    scan_layer0<<<scanGrid, 256>>>(pF, pC, pAh, pAl, hT);

    // Layer 1
    gemm_tc<<<gemmGrid, 512, GEMM_SMEM>>>(pAh, pAl,
                                          pBh + 1048576u, pBl + 1048576u,
                                          bf + H_DIM, bi + H_DIM, pF, pC);
    scan_layer1<<<scanGrid, 256>>>(pF, pC, spikes, hT + BH);
}